// round 5
// baseline (speedup 1.0000x reference)
#include <cuda_runtime.h>

#define BATCH 4
#define SEQ   8192
#define DM    1024
#define DK    128
#define NB    (BATCH*SEQ)   // 32768 total rows
#define NSLICE 8            // split-n slices for k_m

// Scratch (device globals -- no dynamic allocation allowed)
__device__ float g_Q [(size_t)NB * DK];                    // 16 MB
__device__ float g_K [(size_t)NB * DK];                    // 16 MB
__device__ float g_Mp[(size_t)BATCH * NSLICE * DK * DM];   // 16 MB (partials)
__device__ float g_M [(size_t)BATCH * DK * DM];            // 2 MB
__device__ float g_Jn[(size_t)NB * DM];                    // 128 MB

// ---------------------------------------------------------------------------
// Shared 8x8-microtile FMA block (128x128 tile, BK=8)
// ---------------------------------------------------------------------------
#define MICRO_FMA(As_, Bs_, r0_, r1_, c0_, c1_, acc_)                          \
    _Pragma("unroll")                                                          \
    for (int kk = 0; kk < 8; kk++) {                                           \
        float4 a0 = *(const float4*)&As_[kk][r0_];                             \
        float4 a1 = *(const float4*)&As_[kk][r1_];                             \
        float4 b0 = *(const float4*)&Bs_[kk][c0_];                             \
        float4 b1 = *(const float4*)&Bs_[kk][c1_];                             \
        float av[2][4] = {{a0.x,a0.y,a0.z,a0.w},{a1.x,a1.y,a1.z,a1.w}};        \
        float bv[2][4] = {{b0.x,b0.y,b0.z,b0.w},{b1.x,b1.y,b1.z,b1.w}};        \
        _Pragma("unroll")                                                      \
        for (int im = 0; im < 2; im++)                                         \
        _Pragma("unroll")                                                      \
        for (int i = 0; i < 4; i++)                                            \
        _Pragma("unroll")                                                      \
        for (int jm = 0; jm < 2; jm++)                                         \
        _Pragma("unroll")                                                      \
        for (int j = 0; j < 4; j++)                                            \
            acc_[im][jm][i][j] += av[im][i] * bv[jm][j];                       \
    }

// ---------------------------------------------------------------------------
// Kernel 1: Q|K projection. C[m][j] = sum_d J[m][d] * W[j][d]
// blockIdx.y == 0 -> W_Q / g_Q ; == 1 -> W_K / g_K.
// Tile 128x128, BK=8, double-buffered smem, reg-staged prefetch.
// ---------------------------------------------------------------------------
__global__ void __launch_bounds__(256) k_qk(const float* __restrict__ J,
                                            const float* __restrict__ WQ,
                                            const float* __restrict__ WK) {
    __shared__ float As[2][8][128];   // As[buf][k][m]
    __shared__ float Bs[2][8][128];   // Bs[buf][k][j]
    const int t  = threadIdx.x;
    const int m0 = blockIdx.x * 128;
    const float* W = (blockIdx.y == 0) ? WQ : WK;
    float* OUT     = (blockIdx.y == 0) ? g_Q : g_K;

    const int lr = t >> 1;            // 0..127
    const int lk = (t & 1) << 2;      // 0 or 4

    const int ty = t >> 4, tx = t & 15;
    const int r0 = ty << 2, r1 = r0 + 64;
    const int c0 = tx << 2, c1 = c0 + 64;

    const float* abase = J + (size_t)(m0 + lr) * DM + lk;
    const float* bbase = W + (size_t)lr * DM + lk;

    // prologue: tile 0 -> buf 0
    {
        float4 va = *(const float4*)(abase);
        float4 vb = *(const float4*)(bbase);
        As[0][lk+0][lr]=va.x; As[0][lk+1][lr]=va.y; As[0][lk+2][lr]=va.z; As[0][lk+3][lr]=va.w;
        Bs[0][lk+0][lr]=vb.x; Bs[0][lk+1][lr]=vb.y; Bs[0][lk+2][lr]=vb.z; Bs[0][lk+3][lr]=vb.w;
    }
    __syncthreads();

    float acc[2][2][4][4] = {};
    int buf = 0;
    for (int k0 = 0; k0 < DM; k0 += 8) {
        float4 na, nb;
        const bool hn = (k0 + 8) < DM;
        if (hn) {
            na = *(const float4*)(abase + k0 + 8);
            nb = *(const float4*)(bbase + k0 + 8);
        }
        MICRO_FMA(As[buf], Bs[buf], r0, r1, c0, c1, acc);
        if (hn) {
            const int nb_ = buf ^ 1;
            As[nb_][lk+0][lr]=na.x; As[nb_][lk+1][lr]=na.y; As[nb_][lk+2][lr]=na.z; As[nb_][lk+3][lr]=na.w;
            Bs[nb_][lk+0][lr]=nb.x; Bs[nb_][lk+1][lr]=nb.y; Bs[nb_][lk+2][lr]=nb.z; Bs[nb_][lk+3][lr]=nb.w;
        }
        __syncthreads();
        buf ^= 1;
    }
#pragma unroll
    for (int im = 0; im < 2; im++)
#pragma unroll
    for (int i = 0; i < 4; i++) {
        const size_t m = (size_t)(m0 + (im ? r1 : r0) + i);
#pragma unroll
        for (int jm = 0; jm < 2; jm++) {
            const int c = jm ? c1 : c0;
            float4 o = make_float4(acc[im][jm][i][0], acc[im][jm][i][1],
                                   acc[im][jm][i][2], acc[im][jm][i][3]);
            *(float4*)(OUT + m * DK + c) = o;
        }
    }
}

// ---------------------------------------------------------------------------
// Kernel 2: partial M. Mp[b][s][k][d] = sum_{n in slice s} K[b][n][k]*J[b][n][d]
// Tile 128(k) x 128(d), n-chunk 8, slice = 1024 rows of n, double-buffered.
// grid: (DM/128, NSLICE, BATCH)
// ---------------------------------------------------------------------------
__global__ void __launch_bounds__(256) k_m(const float* __restrict__ J) {
    __shared__ float Ks[2][8][128];   // Ks[buf][n][k]
    __shared__ float Js[2][8][128];   // Js[buf][n][d]
    const int t  = threadIdx.x;
    const int d0 = blockIdx.x * 128;
    const int s  = blockIdx.y;
    const int b  = blockIdx.z;

    const int ln = t >> 5;            // 0..7
    const int lc = (t & 31) << 2;     // 0..124

    const int ty = t >> 4, tx = t & 15;
    const int r0 = ty << 2, r1 = r0 + 64;   // k dim
    const int c0 = tx << 2, c1 = c0 + 64;   // d dim

    const int nbeg = s * (SEQ / NSLICE);
    const int nend = nbeg + (SEQ / NSLICE);
    const float* Kb = g_K + (size_t)b * SEQ * DK + lc;
    const float* Jb = J   + (size_t)b * SEQ * DM + d0 + lc;

    // prologue
    *(float4*)&Ks[0][ln][lc] = *(const float4*)(Kb + (size_t)(nbeg + ln) * DK);
    *(float4*)&Js[0][ln][lc] = *(const float4*)(Jb + (size_t)(nbeg + ln) * DM);
    __syncthreads();

    float acc[2][2][4][4] = {};
    int buf = 0;
    for (int n0 = nbeg; n0 < nend; n0 += 8) {
        float4 nk, nj;
        const bool hn = (n0 + 8) < nend;
        if (hn) {
            nk = *(const float4*)(Kb + (size_t)(n0 + 8 + ln) * DK);
            nj = *(const float4*)(Jb + (size_t)(n0 + 8 + ln) * DM);
        }
        MICRO_FMA(Ks[buf], Js[buf], r0, r1, c0, c1, acc);
        if (hn) {
            const int nb_ = buf ^ 1;
            *(float4*)&Ks[nb_][ln][lc] = nk;
            *(float4*)&Js[nb_][ln][lc] = nj;
        }
        __syncthreads();
        buf ^= 1;
    }
    float* Mp = g_Mp + ((size_t)(b * NSLICE + s) * DK) * DM;
#pragma unroll
    for (int im = 0; im < 2; im++)
#pragma unroll
    for (int i = 0; i < 4; i++) {
        const int k = (im ? r1 : r0) + i;
#pragma unroll
        for (int jm = 0; jm < 2; jm++) {
            const int c = d0 + (jm ? c1 : c0);
            float4 o = make_float4(acc[im][jm][i][0], acc[im][jm][i][1],
                                   acc[im][jm][i][2], acc[im][jm][i][3]);
            *(float4*)(Mp + (size_t)k * DM + c) = o;
        }
    }
}

// ---------------------------------------------------------------------------
// Kernel 2b: reduce slices.  M[b][k][d] = sum_s Mp[b][s][k][d]
// ---------------------------------------------------------------------------
__global__ void __launch_bounds__(256) k_mred() {
    const size_t f = (size_t)blockIdx.x * 256 + threadIdx.x;  // float4 index
    const size_t base = f * 4;
    const size_t per_b = (size_t)DK * DM;
    const size_t b = base / per_b;
    const size_t rem = base % per_b;
    float4 acc = make_float4(0.f, 0.f, 0.f, 0.f);
#pragma unroll
    for (int s = 0; s < NSLICE; s++) {
        float4 v = *(const float4*)(g_Mp + (b * NSLICE + s) * per_b + rem);
        acc.x += v.x; acc.y += v.y; acc.z += v.z; acc.w += v.w;
    }
    *(float4*)(g_M + b * per_b + rem) = acc;
}

// ---------------------------------------------------------------------------
// Kernel 3: J_new[m][d] = (1/sqrt(128)) * sum_k Q[m][k]*M[b][k][d] + J[m][d]
// Tile 128x128, BK=8 (16 iters), double-buffered.
// ---------------------------------------------------------------------------
__global__ void __launch_bounds__(256) k_out(const float* __restrict__ J) {
    __shared__ float As[2][8][128];   // As[buf][k][m] (transposed Q tile)
    __shared__ float Bs[2][8][128];   // Bs[buf][k][d] (direct M tile)
    const int t  = threadIdx.x;
    const int m0 = blockIdx.x * 128;
    const int d0 = blockIdx.y * 128;
    const int b  = m0 / SEQ;

    const int lrA = t >> 1;            // 0..127 (m)
    const int lkA = (t & 1) << 2;      // 0 or 4 (k)
    const int lkB = t >> 5;            // 0..7   (k)
    const int lcB = (t & 31) << 2;     // 0..124 (d)

    const int ty = t >> 4, tx = t & 15;
    const int r0 = ty << 2, r1 = r0 + 64;
    const int c0 = tx << 2, c1 = c0 + 64;

    const float* Mb = g_M + (size_t)b * DK * DM + d0 + lcB;
    const float* qbase = g_Q + (size_t)(m0 + lrA) * DK + lkA;

    // prologue
    {
        float4 va = *(const float4*)(qbase);
        As[0][lkA+0][lrA]=va.x; As[0][lkA+1][lrA]=va.y; As[0][lkA+2][lrA]=va.z; As[0][lkA+3][lrA]=va.w;
        *(float4*)&Bs[0][lkB][lcB] = *(const float4*)(Mb + (size_t)lkB * DM);
    }
    __syncthreads();

    float acc[2][2][4][4] = {};
    int buf = 0;
    for (int k0 = 0; k0 < DK; k0 += 8) {
        float4 na, nb;
        const bool hn = (k0 + 8) < DK;
        if (hn) {
            na = *(const float4*)(qbase + k0 + 8);
            nb = *(const float4*)(Mb + (size_t)(k0 + 8 + lkB) * DM);
        }
        MICRO_FMA(As[buf], Bs[buf], r0, r1, c0, c1, acc);
        if (hn) {
            const int nb_ = buf ^ 1;
            As[nb_][lkA+0][lrA]=na.x; As[nb_][lkA+1][lrA]=na.y; As[nb_][lkA+2][lrA]=na.z; As[nb_][lkA+3][lrA]=na.w;
            *(float4*)&Bs[nb_][lkB][lcB] = nb;
        }
        __syncthreads();
        buf ^= 1;
    }
    const float sc = 0.088388347648318447f;  // 1/sqrt(128)
#pragma unroll
    for (int im = 0; im < 2; im++)
#pragma unroll
    for (int i = 0; i < 4; i++) {
        const size_t m = (size_t)(m0 + (im ? r1 : r0) + i);
#pragma unroll
        for (int jm = 0; jm < 2; jm++) {
            const int dd = d0 + (jm ? c1 : c0);
            float4 jv = *(const float4*)(J + m * DM + dd);
            float4 o;
            o.x = acc[im][jm][i][0] * sc + jv.x;
            o.y = acc[im][jm][i][1] * sc + jv.y;
            o.z = acc[im][jm][i][2] * sc + jv.z;
            o.w = acc[im][jm][i][3] * sc + jv.w;
            *(float4*)(g_Jn + m * DM + dd) = o;
        }
    }
}

// ---------------------------------------------------------------------------
// Kernel 4: LayerNorm over last dim (1024). One block (256 thr) per row.
// ---------------------------------------------------------------------------
__global__ void __launch_bounds__(256) k_ln(const float* __restrict__ gamma,
                                            const float* __restrict__ beta,
                                            float* __restrict__ out) {
    __shared__ float sred[8], ssred[8];
    const int t = threadIdx.x;
    const size_t row = blockIdx.x;
    const int dd = t << 2;

    float4 v = *(const float4*)(g_Jn + row * DM + dd);
    float s  = v.x + v.y + v.z + v.w;
    float ss = v.x * v.x + v.y * v.y + v.z * v.z + v.w * v.w;
#pragma unroll
    for (int o = 16; o > 0; o >>= 1) {
        s  += __shfl_xor_sync(0xffffffffu, s,  o);
        ss += __shfl_xor_sync(0xffffffffu, ss, o);
    }
    const int w = t >> 5;
    if ((t & 31) == 0) { sred[w] = s; ssred[w] = ss; }
    __syncthreads();
    s = 0.f; ss = 0.f;
#pragma unroll
    for (int i = 0; i < 8; i++) { s += sred[i]; ss += ssred[i]; }

    const float mean = s * (1.0f / DM);
    const float var  = ss * (1.0f / DM) - mean * mean;
    const float rstd = rsqrtf(var + 1e-5f);

    float4 g = *(const float4*)(gamma + dd);
    float4 b = *(const float4*)(beta + dd);
    float4 o;
    o.x = (v.x - mean) * rstd * g.x + b.x;
    o.y = (v.y - mean) * rstd * g.y + b.y;
    o.z = (v.z - mean) * rstd * g.z + b.z;
    o.w = (v.w - mean) * rstd * g.w + b.w;
    *(float4*)(out + row * DM + dd) = o;
}

// ---------------------------------------------------------------------------
extern "C" void kernel_launch(void* const* d_in, const int* in_sizes, int n_in,
                              void* d_out, int out_size) {
    (void)in_sizes; (void)n_in; (void)out_size;
    const float* J     = (const float*)d_in[0];
    const float* WQ    = (const float*)d_in[1];
    const float* WK    = (const float*)d_in[2];
    const float* gamma = (const float*)d_in[3];
    const float* beta  = (const float*)d_in[4];
    float* out = (float*)d_out;

    k_qk  <<<dim3(NB / 128, 2), 256>>>(J, WQ, WK);
    k_m   <<<dim3(DM / 128, NSLICE, BATCH), 256>>>(J);
    k_mred<<<(BATCH * DK * DM / 4) / 256, 256>>>();
    k_out <<<dim3(NB / 128, DM / 128), 256>>>(J);
    k_ln  <<<NB, 256>>>(gamma, beta, out);
}

// round 7
// speedup vs baseline: 1.7109x; 1.7109x over previous
#include <cuda_runtime.h>
#include <cstdint>

#define BATCH 4
#define SEQ   8192
#define DM    1024
#define DK    128
#define NB    (BATCH*SEQ)   // 32768 total rows
#define NSLICE 8            // split-n slices for k_m
#define PADW  136           // smem row stride in floats (128 + 8): conflict-free frags

// Scratch (device globals -- no dynamic allocation allowed)
__device__ float g_Q [(size_t)NB * DK];                    // 16 MB
__device__ float g_K [(size_t)NB * DK];                    // 16 MB
__device__ float g_Mp[(size_t)BATCH * NSLICE * DK * DM];   // 16 MB (partials)
__device__ float g_M [(size_t)BATCH * DK * DM];            // 2 MB
__device__ float g_Jn[(size_t)NB * DM];                    // 128 MB

__device__ __forceinline__ float tf32r(float x) {
    float y;
    asm("cvt.rna.tf32.f32 %0, %1;" : "=f"(y) : "f"(x));
    return y;
}

// ---------------------------------------------------------------------------
// Canonical tf32 MMA step on smem tiles As_[8][PADW] (k x m), Bs_[8][PADW] (k x n).
// Block tile 128x128, 8 warps as 2(m) x 4(n); warp tile 64(m) x 32(n).
// Per warp: 4 m16-frags x 4 n8-frags = 16 x mma.m16n8k8 per k=8 step.
// Needs in scope: g (lane>>2), tg (lane&3), am (wm*64+g), bn (wn*32+g),
//                 float acc[4][4][4].
// ---------------------------------------------------------------------------
#define MMA_STEP(As_, Bs_) do {                                                 \
    uint32_t afr[4][4], bfr[4][2];                                              \
    _Pragma("unroll")                                                           \
    for (int im = 0; im < 4; im++) {                                            \
        const uint32_t* p0 = (const uint32_t*)&As_[tg    ][am + im * 16];       \
        const uint32_t* p1 = (const uint32_t*)&As_[tg + 4][am + im * 16];       \
        afr[im][0] = p0[0]; afr[im][1] = p0[8];                                 \
        afr[im][2] = p1[0]; afr[im][3] = p1[8];                                 \
    }                                                                           \
    _Pragma("unroll")                                                           \
    for (int jn = 0; jn < 4; jn++) {                                            \
        bfr[jn][0] = *(const uint32_t*)&Bs_[tg    ][bn + jn * 8];               \
        bfr[jn][1] = *(const uint32_t*)&Bs_[tg + 4][bn + jn * 8];               \
    }                                                                           \
    _Pragma("unroll")                                                           \
    for (int im = 0; im < 4; im++)                                              \
    _Pragma("unroll")                                                           \
    for (int jn = 0; jn < 4; jn++)                                              \
        asm volatile(                                                           \
            "mma.sync.aligned.m16n8k8.row.col.f32.tf32.tf32.f32 "               \
            "{%0,%1,%2,%3}, {%4,%5,%6,%7}, {%8,%9}, {%0,%1,%2,%3};"             \
            : "+f"(acc[im][jn][0]), "+f"(acc[im][jn][1]),                       \
              "+f"(acc[im][jn][2]), "+f"(acc[im][jn][3])                        \
            : "r"(afr[im][0]), "r"(afr[im][1]), "r"(afr[im][2]),                \
              "r"(afr[im][3]), "r"(bfr[jn][0]), "r"(bfr[jn][1]));               \
} while (0)

#define WARP_IDX()                                                              \
    const int lane = t & 31;                                                    \
    const int w  = t >> 5;                                                      \
    const int wm = w & 1;                                                       \
    const int wn = w >> 1;                                                      \
    const int g  = lane >> 2;                                                   \
    const int tg = lane & 3;                                                    \
    const int am = wm * 64 + g;                                                 \
    const int bn = wn * 32 + g;

// ---------------------------------------------------------------------------
// Kernel 1: Q|K projection. C[m][j] = sum_d J[m][d] * W[j][d]
// blockIdx.y == 0 -> W_Q / g_Q ; == 1 -> W_K / g_K.
// ---------------------------------------------------------------------------
__global__ void __launch_bounds__(256) k_qk(const float* __restrict__ J,
                                            const float* __restrict__ WQ,
                                            const float* __restrict__ WK) {
    __shared__ float As[2][8][PADW];   // [buf][k][m]
    __shared__ float Bs[2][8][PADW];   // [buf][k][j]
    const int t  = threadIdx.x;
    const int m0 = blockIdx.x * 128;
    const float* W = (blockIdx.y == 0) ? WQ : WK;
    float* OUT     = (blockIdx.y == 0) ? g_Q : g_K;

    const int lr = t >> 1;            // 0..127
    const int lk = (t & 1) << 2;      // 0 or 4
    WARP_IDX();

    const float* abase = J + (size_t)(m0 + lr) * DM + lk;
    const float* bbase = W + (size_t)lr * DM + lk;

    {   // prologue: tile 0 -> buf 0 (converted to tf32 at staging)
        float4 va = *(const float4*)(abase);
        float4 vb = *(const float4*)(bbase);
        As[0][lk+0][lr]=tf32r(va.x); As[0][lk+1][lr]=tf32r(va.y);
        As[0][lk+2][lr]=tf32r(va.z); As[0][lk+3][lr]=tf32r(va.w);
        Bs[0][lk+0][lr]=tf32r(vb.x); Bs[0][lk+1][lr]=tf32r(vb.y);
        Bs[0][lk+2][lr]=tf32r(vb.z); Bs[0][lk+3][lr]=tf32r(vb.w);
    }
    __syncthreads();

    float acc[4][4][4] = {};
    int buf = 0;
    for (int k0 = 0; k0 < DM; k0 += 8) {
        float4 na, nb;
        const bool hn = (k0 + 8) < DM;
        if (hn) {
            na = *(const float4*)(abase + k0 + 8);
            nb = *(const float4*)(bbase + k0 + 8);
        }
        MMA_STEP(As[buf], Bs[buf]);
        if (hn) {
            const int nx = buf ^ 1;
            As[nx][lk+0][lr]=tf32r(na.x); As[nx][lk+1][lr]=tf32r(na.y);
            As[nx][lk+2][lr]=tf32r(na.z); As[nx][lk+3][lr]=tf32r(na.w);
            Bs[nx][lk+0][lr]=tf32r(nb.x); Bs[nx][lk+1][lr]=tf32r(nb.y);
            Bs[nx][lk+2][lr]=tf32r(nb.z); Bs[nx][lk+3][lr]=tf32r(nb.w);
        }
        __syncthreads();
        buf ^= 1;
    }
#pragma unroll
    for (int im = 0; im < 4; im++)
#pragma unroll
    for (int jn = 0; jn < 4; jn++) {
        const size_t m = (size_t)(m0 + wm * 64 + im * 16 + g);
        const int    c = wn * 32 + jn * 8 + 2 * tg;
        *(float2*)(OUT + m * DK + c)       = make_float2(acc[im][jn][0], acc[im][jn][1]);
        *(float2*)(OUT + (m + 8) * DK + c) = make_float2(acc[im][jn][2], acc[im][jn][3]);
    }
}

// ---------------------------------------------------------------------------
// Kernel 2: partial M. Mp[b][s][k][d] = sum_{n in slice s} K[b][n][k]*J[b][n][d]
// grid: (DM/128, NSLICE, BATCH); tile 128(k) x 128(d), n-chunk 8.
// ---------------------------------------------------------------------------
__global__ void __launch_bounds__(256) k_m(const float* __restrict__ J) {
    __shared__ float Ks[2][8][PADW];   // [buf][n][k]
    __shared__ float Js[2][8][PADW];   // [buf][n][d]
    const int t  = threadIdx.x;
    const int d0 = blockIdx.x * 128;
    const int s  = blockIdx.y;
    const int b  = blockIdx.z;

    const int ln = t >> 5;            // 0..7
    const int lc = (t & 31) << 2;     // 0..124
    WARP_IDX();

    const int nbeg = s * (SEQ / NSLICE);
    const int nend = nbeg + (SEQ / NSLICE);
    const float* Kb = g_K + (size_t)b * SEQ * DK + lc;
    const float* Jb = J   + (size_t)b * SEQ * DM + d0 + lc;

    {   // prologue
        float4 vk = *(const float4*)(Kb + (size_t)(nbeg + ln) * DK);
        float4 vj = *(const float4*)(Jb + (size_t)(nbeg + ln) * DM);
        Ks[0][ln][lc+0]=tf32r(vk.x); Ks[0][ln][lc+1]=tf32r(vk.y);
        Ks[0][ln][lc+2]=tf32r(vk.z); Ks[0][ln][lc+3]=tf32r(vk.w);
        Js[0][ln][lc+0]=tf32r(vj.x); Js[0][ln][lc+1]=tf32r(vj.y);
        Js[0][ln][lc+2]=tf32r(vj.z); Js[0][ln][lc+3]=tf32r(vj.w);
    }
    __syncthreads();

    float acc[4][4][4] = {};
    int buf = 0;
    for (int n0 = nbeg; n0 < nend; n0 += 8) {
        float4 nk, nj;
        const bool hn = (n0 + 8) < nend;
        if (hn) {
            nk = *(const float4*)(Kb + (size_t)(n0 + 8 + ln) * DK);
            nj = *(const float4*)(Jb + (size_t)(n0 + 8 + ln) * DM);
        }
        MMA_STEP(Ks[buf], Js[buf]);
        if (hn) {
            const int nx = buf ^ 1;
            Ks[nx][ln][lc+0]=tf32r(nk.x); Ks[nx][ln][lc+1]=tf32r(nk.y);
            Ks[nx][ln][lc+2]=tf32r(nk.z); Ks[nx][ln][lc+3]=tf32r(nk.w);
            Js[nx][ln][lc+0]=tf32r(nj.x); Js[nx][ln][lc+1]=tf32r(nj.y);
            Js[nx][ln][lc+2]=tf32r(nj.z); Js[nx][ln][lc+3]=tf32r(nj.w);
        }
        __syncthreads();
        buf ^= 1;
    }
    float* Mp = g_Mp + ((size_t)(b * NSLICE + s) * DK) * DM;
#pragma unroll
    for (int im = 0; im < 4; im++)
#pragma unroll
    for (int jn = 0; jn < 4; jn++) {
        const int k = wm * 64 + im * 16 + g;
        const int c = d0 + wn * 32 + jn * 8 + 2 * tg;
        *(float2*)(Mp + (size_t)k * DM + c)       = make_float2(acc[im][jn][0], acc[im][jn][1]);
        *(float2*)(Mp + (size_t)(k + 8) * DM + c) = make_float2(acc[im][jn][2], acc[im][jn][3]);
    }
}

// ---------------------------------------------------------------------------
// Kernel 2b: reduce slices.  M[b][k][d] = sum_s Mp[b][s][k][d]
// ---------------------------------------------------------------------------
__global__ void __launch_bounds__(256) k_mred() {
    const size_t f = (size_t)blockIdx.x * 256 + threadIdx.x;  // float4 index
    const size_t base = f * 4;
    const size_t per_b = (size_t)DK * DM;
    const size_t b = base / per_b;
    const size_t rem = base % per_b;
    float4 acc = make_float4(0.f, 0.f, 0.f, 0.f);
#pragma unroll
    for (int s = 0; s < NSLICE; s++) {
        float4 v = *(const float4*)(g_Mp + (b * NSLICE + s) * per_b + rem);
        acc.x += v.x; acc.y += v.y; acc.z += v.z; acc.w += v.w;
    }
    *(float4*)(g_M + b * per_b + rem) = acc;
}

// ---------------------------------------------------------------------------
// Kernel 3: J_new[m][d] = (1/sqrt(128)) * sum_k Q[m][k]*M[b][k][d] + J[m][d]
// Tile 128x128, 16 k-iters of 8.
// ---------------------------------------------------------------------------
__global__ void __launch_bounds__(256) k_out(const float* __restrict__ J) {
    __shared__ float As[2][8][PADW];   // [buf][k][m] (transposed Q tile)
    __shared__ float Bs[2][8][PADW];   // [buf][k][d]
    const int t  = threadIdx.x;
    const int m0 = blockIdx.x * 128;
    const int d0 = blockIdx.y * 128;
    const int b  = m0 / SEQ;

    const int lrA = t >> 1;            // 0..127 (m)
    const int lkA = (t & 1) << 2;      // 0 or 4 (k)
    const int lkB = t >> 5;            // 0..7   (k)
    const int lcB = (t & 31) << 2;     // 0..124 (d)
    WARP_IDX();

    const float* Mb = g_M + (size_t)b * DK * DM + d0 + lcB;
    const float* qbase = g_Q + (size_t)(m0 + lrA) * DK + lkA;

    {   // prologue
        float4 va = *(const float4*)(qbase);
        float4 vb = *(const float4*)(Mb + (size_t)lkB * DM);
        As[0][lkA+0][lrA]=tf32r(va.x); As[0][lkA+1][lrA]=tf32r(va.y);
        As[0][lkA+2][lrA]=tf32r(va.z); As[0][lkA+3][lrA]=tf32r(va.w);
        Bs[0][lkB][lcB+0]=tf32r(vb.x); Bs[0][lkB][lcB+1]=tf32r(vb.y);
        Bs[0][lkB][lcB+2]=tf32r(vb.z); Bs[0][lkB][lcB+3]=tf32r(vb.w);
    }
    __syncthreads();

    float acc[4][4][4] = {};
    int buf = 0;
    for (int k0 = 0; k0 < DK; k0 += 8) {
        float4 na, nb;
        const bool hn = (k0 + 8) < DK;
        if (hn) {
            na = *(const float4*)(qbase + k0 + 8);
            nb = *(const float4*)(Mb + (size_t)(k0 + 8 + lkB) * DM);
        }
        MMA_STEP(As[buf], Bs[buf]);
        if (hn) {
            const int nx = buf ^ 1;
            As[nx][lkA+0][lrA]=tf32r(na.x); As[nx][lkA+1][lrA]=tf32r(na.y);
            As[nx][lkA+2][lrA]=tf32r(na.z); As[nx][lkA+3][lrA]=tf32r(na.w);
            Bs[nx][lkB][lcB+0]=tf32r(nb.x); Bs[nx][lkB][lcB+1]=tf32r(nb.y);
            Bs[nx][lkB][lcB+2]=tf32r(nb.z); Bs[nx][lkB][lcB+3]=tf32r(nb.w);
        }
        __syncthreads();
        buf ^= 1;
    }
    const float sc = 0.088388347648318447f;  // 1/sqrt(128)
#pragma unroll
    for (int im = 0; im < 4; im++)
#pragma unroll
    for (int jn = 0; jn < 4; jn++) {
        const size_t m  = (size_t)(m0 + wm * 64 + im * 16 + g);
        const int    dd = d0 + wn * 32 + jn * 8 + 2 * tg;
        float2 j0 = *(const float2*)(J + m * DM + dd);
        float2 j1 = *(const float2*)(J + (m + 8) * DM + dd);
        *(float2*)(g_Jn + m * DM + dd) =
            make_float2(acc[im][jn][0] * sc + j0.x, acc[im][jn][1] * sc + j0.y);
        *(float2*)(g_Jn + (m + 8) * DM + dd) =
            make_float2(acc[im][jn][2] * sc + j1.x, acc[im][jn][3] * sc + j1.y);
    }
}

// ---------------------------------------------------------------------------
// Kernel 4: LayerNorm over last dim (1024). One block (256 thr) per row.
// ---------------------------------------------------------------------------
__global__ void __launch_bounds__(256) k_ln(const float* __restrict__ gamma,
                                            const float* __restrict__ beta,
                                            float* __restrict__ out) {
    __shared__ float sred[8], ssred[8];
    const int t = threadIdx.x;
    const size_t row = blockIdx.x;
    const int dd = t << 2;

    float4 v = *(const float4*)(g_Jn + row * DM + dd);
    float s  = v.x + v.y + v.z + v.w;
    float ss = v.x * v.x + v.y * v.y + v.z * v.z + v.w * v.w;
#pragma unroll
    for (int o = 16; o > 0; o >>= 1) {
        s  += __shfl_xor_sync(0xffffffffu, s,  o);
        ss += __shfl_xor_sync(0xffffffffu, ss, o);
    }
    const int w = t >> 5;
    if ((t & 31) == 0) { sred[w] = s; ssred[w] = ss; }
    __syncthreads();
    s = 0.f; ss = 0.f;
#pragma unroll
    for (int i = 0; i < 8; i++) { s += sred[i]; ss += ssred[i]; }

    const float mean = s * (1.0f / DM);
    const float var  = ss * (1.0f / DM) - mean * mean;
    const float rstd = rsqrtf(var + 1e-5f);

    float4 g = *(const float4*)(gamma + dd);
    float4 b = *(const float4*)(beta + dd);
    float4 o;
    o.x = (v.x - mean) * rstd * g.x + b.x;
    o.y = (v.y - mean) * rstd * g.y + b.y;
    o.z = (v.z - mean) * rstd * g.z + b.z;
    o.w = (v.w - mean) * rstd * g.w + b.w;
    *(float4*)(out + row * DM + dd) = o;
}

// ---------------------------------------------------------------------------
extern "C" void kernel_launch(void* const* d_in, const int* in_sizes, int n_in,
                              void* d_out, int out_size) {
    (void)in_sizes; (void)n_in; (void)out_size;
    const float* J     = (const float*)d_in[0];
    const float* WQ    = (const float*)d_in[1];
    const float* WK    = (const float*)d_in[2];
    const float* gamma = (const float*)d_in[3];
    const float* beta  = (const float*)d_in[4];
    float* out = (float*)d_out;

    k_qk  <<<dim3(NB / 128, 2), 256>>>(J, WQ, WK);
    k_m   <<<dim3(DM / 128, NSLICE, BATCH), 256>>>(J);
    k_mred<<<(BATCH * DK * DM / 4) / 256, 256>>>();
    k_out <<<dim3(NB / 128, DM / 128), 256>>>(J);
    k_ln  <<<NB, 256>>>(gamma, beta, out);
}

// round 8
// speedup vs baseline: 1.8347x; 1.0724x over previous
#include <cuda_runtime.h>
#include <cstdint>

#define BATCH 4
#define SEQ   8192
#define DM    1024
#define DK    128
#define NB    (BATCH*SEQ)   // 32768 total rows
#define NSLICE 8            // split-n slices for k_m
#define PADW  136           // smem row stride in floats: conflict-free frags

// Scratch (device globals -- no dynamic allocation allowed)
__device__ float g_Q [(size_t)NB * DK];                    // 16 MB
__device__ float g_K [(size_t)NB * DK];                    // 16 MB
__device__ float g_Mp[(size_t)BATCH * NSLICE * DK * DM];   // 16 MB (partials)
__device__ float g_M [(size_t)BATCH * DK * DM];            // 2 MB
__device__ float g_Jn[(size_t)NB * DM];                    // 128 MB

__device__ __forceinline__ float tf32r(float x) {
    float y;
    asm("cvt.rna.tf32.f32 %0, %1;" : "=f"(y) : "f"(x));
    return y;
}
__device__ __forceinline__ float4 tf32r4(float4 v) {
    return make_float4(tf32r(v.x), tf32r(v.y), tf32r(v.z), tf32r(v.w));
}

// ---------------------------------------------------------------------------
// One 8-k MMA microstep on smem tiles As_[16][PADW] (k x m), Bs_[16][PADW]
// (k x n), fragment rows ks_..ks_+7. Block tile 128x128; 8 warps = 2(m)x4(n);
// warp tile 64(m) x 32(n): 16 x mma.m16n8k8 per microstep.
// Needs in scope: g, tg, am, bn, float acc[4][4][4].
// ---------------------------------------------------------------------------
#define MMA_STEP8(As_, Bs_, ks_) do {                                           \
    uint32_t afr[4][4], bfr[4][2];                                              \
    _Pragma("unroll")                                                           \
    for (int im = 0; im < 4; im++) {                                            \
        const uint32_t* p0 = (const uint32_t*)&As_[(ks_) + tg    ][am + im*16]; \
        const uint32_t* p1 = (const uint32_t*)&As_[(ks_) + tg + 4][am + im*16]; \
        afr[im][0] = p0[0]; afr[im][1] = p0[8];                                 \
        afr[im][2] = p1[0]; afr[im][3] = p1[8];                                 \
    }                                                                           \
    _Pragma("unroll")                                                           \
    for (int jn = 0; jn < 4; jn++) {                                            \
        bfr[jn][0] = *(const uint32_t*)&Bs_[(ks_) + tg    ][bn + jn * 8];       \
        bfr[jn][1] = *(const uint32_t*)&Bs_[(ks_) + tg + 4][bn + jn * 8];       \
    }                                                                           \
    _Pragma("unroll")                                                           \
    for (int im = 0; im < 4; im++)                                              \
    _Pragma("unroll")                                                           \
    for (int jn = 0; jn < 4; jn++)                                              \
        asm volatile(                                                           \
            "mma.sync.aligned.m16n8k8.row.col.f32.tf32.tf32.f32 "               \
            "{%0,%1,%2,%3}, {%4,%5,%6,%7}, {%8,%9}, {%0,%1,%2,%3};"             \
            : "+f"(acc[im][jn][0]), "+f"(acc[im][jn][1]),                       \
              "+f"(acc[im][jn][2]), "+f"(acc[im][jn][3])                        \
            : "r"(afr[im][0]), "r"(afr[im][1]), "r"(afr[im][2]),                \
              "r"(afr[im][3]), "r"(bfr[jn][0]), "r"(bfr[jn][1]));               \
} while (0)

#define WARP_IDX()                                                              \
    const int lane = t & 31;                                                    \
    const int w  = t >> 5;                                                      \
    const int wm = w & 1;                                                       \
    const int wn = w >> 1;                                                      \
    const int g  = lane >> 2;                                                   \
    const int tg = lane & 3;                                                    \
    const int am = wm * 64 + g;                                                 \
    const int bn = wn * 32 + g;

// transposed scalar store of a float4 (k-major -> [k][m] tile)
#define STS_T4(T_, kbase_, mrow_, v_)                                           \
    T_[(kbase_) + 0][mrow_] = (v_).x; T_[(kbase_) + 1][mrow_] = (v_).y;         \
    T_[(kbase_) + 2][mrow_] = (v_).z; T_[(kbase_) + 3][mrow_] = (v_).w;

// ---------------------------------------------------------------------------
// Kernel 1: Q|K projection. C[m][j] = sum_d J[m][d] * W[j][d]
// blockIdx.y == 0 -> W_Q / g_Q ; == 1 -> W_K / g_K.  BK=16, double-buffered.
// ---------------------------------------------------------------------------
__global__ void __launch_bounds__(256, 2) k_qk(const float* __restrict__ J,
                                               const float* __restrict__ WQ,
                                               const float* __restrict__ WK) {
    __shared__ float As[2][16][PADW];   // [buf][k][m]
    __shared__ float Bs[2][16][PADW];   // [buf][k][j]
    const int t  = threadIdx.x;
    const int m0 = blockIdx.x * 128;
    const float* W = (blockIdx.y == 0) ? WQ : WK;
    float* OUT     = (blockIdx.y == 0) ? g_Q : g_K;

    const int lr = t >> 1;            // 0..127 (row)
    const int lk = (t & 1) << 2;      // 0 or 4 (k sub-offset; +8 for 2nd half)
    WARP_IDX();

    const float* abase = J + (size_t)(m0 + lr) * DM + lk;
    const float* bbase = W + (size_t)lr * DM + lk;

    {   // prologue: tile 0 -> buf 0
        float4 a0 = tf32r4(*(const float4*)(abase));
        float4 a1 = tf32r4(*(const float4*)(abase + 8));
        float4 b0 = tf32r4(*(const float4*)(bbase));
        float4 b1 = tf32r4(*(const float4*)(bbase + 8));
        STS_T4(As[0], lk,     lr, a0); STS_T4(As[0], lk + 8, lr, a1);
        STS_T4(Bs[0], lk,     lr, b0); STS_T4(Bs[0], lk + 8, lr, b1);
    }
    __syncthreads();

    float acc[4][4][4] = {};
    int buf = 0;
    for (int k0 = 0; k0 < DM; k0 += 16) {
        const bool hn = (k0 + 16) < DM;
        const int nx = buf ^ 1;
        float4 na0, na1;
        if (hn) {
            na0 = *(const float4*)(abase + k0 + 16);
            na1 = *(const float4*)(abase + k0 + 24);
        }
        MMA_STEP8(As[buf], Bs[buf], 0);
        float4 nb0, nb1;
        if (hn) {
            STS_T4(As[nx], lk,     lr, tf32r4(na0));
            STS_T4(As[nx], lk + 8, lr, tf32r4(na1));
            nb0 = *(const float4*)(bbase + k0 + 16);
            nb1 = *(const float4*)(bbase + k0 + 24);
        }
        MMA_STEP8(As[buf], Bs[buf], 8);
        if (hn) {
            STS_T4(Bs[nx], lk,     lr, tf32r4(nb0));
            STS_T4(Bs[nx], lk + 8, lr, tf32r4(nb1));
        }
        __syncthreads();
        buf = nx;
    }
#pragma unroll
    for (int im = 0; im < 4; im++)
#pragma unroll
    for (int jn = 0; jn < 4; jn++) {
        const size_t m = (size_t)(m0 + wm * 64 + im * 16 + g);
        const int    c = wn * 32 + jn * 8 + 2 * tg;
        *(float2*)(OUT + m * DK + c)       = make_float2(acc[im][jn][0], acc[im][jn][1]);
        *(float2*)(OUT + (m + 8) * DK + c) = make_float2(acc[im][jn][2], acc[im][jn][3]);
    }
}

// ---------------------------------------------------------------------------
// Kernel 2: partial M. Mp[b][s][k][d] = sum_{n in slice s} K[b][n][k]*J[b][n][d]
// grid: (DM/128, NSLICE, BATCH); tile 128(k) x 128(d), n-chunk 16.
// ---------------------------------------------------------------------------
__global__ void __launch_bounds__(256, 2) k_m(const float* __restrict__ J) {
    __shared__ float Ks[2][16][PADW];   // [buf][n][k]
    __shared__ float Js[2][16][PADW];   // [buf][n][d]
    const int t  = threadIdx.x;
    const int d0 = blockIdx.x * 128;
    const int s  = blockIdx.y;
    const int b  = blockIdx.z;

    const int ln = t >> 5;            // 0..7 (covers rows ln, ln+8)
    const int lc = (t & 31) << 2;     // 0..124
    WARP_IDX();

    const int nbeg = s * (SEQ / NSLICE);
    const int nend = nbeg + (SEQ / NSLICE);
    const float* Kb = g_K + (size_t)b * SEQ * DK + lc;
    const float* Jb = J   + (size_t)b * SEQ * DM + d0 + lc;

    {   // prologue
        *(float4*)&Ks[0][ln    ][lc] = tf32r4(*(const float4*)(Kb + (size_t)(nbeg + ln    ) * DK));
        *(float4*)&Ks[0][ln + 8][lc] = tf32r4(*(const float4*)(Kb + (size_t)(nbeg + ln + 8) * DK));
        *(float4*)&Js[0][ln    ][lc] = tf32r4(*(const float4*)(Jb + (size_t)(nbeg + ln    ) * DM));
        *(float4*)&Js[0][ln + 8][lc] = tf32r4(*(const float4*)(Jb + (size_t)(nbeg + ln + 8) * DM));
    }
    __syncthreads();

    float acc[4][4][4] = {};
    int buf = 0;
    for (int n0 = nbeg; n0 < nend; n0 += 16) {
        const bool hn = (n0 + 16) < nend;
        const int nx = buf ^ 1;
        float4 nk0, nk1;
        if (hn) {
            nk0 = *(const float4*)(Kb + (size_t)(n0 + 16 + ln    ) * DK);
            nk1 = *(const float4*)(Kb + (size_t)(n0 + 16 + ln + 8) * DK);
        }
        MMA_STEP8(Ks[buf], Js[buf], 0);
        float4 nj0, nj1;
        if (hn) {
            *(float4*)&Ks[nx][ln    ][lc] = tf32r4(nk0);
            *(float4*)&Ks[nx][ln + 8][lc] = tf32r4(nk1);
            nj0 = *(const float4*)(Jb + (size_t)(n0 + 16 + ln    ) * DM);
            nj1 = *(const float4*)(Jb + (size_t)(n0 + 16 + ln + 8) * DM);
        }
        MMA_STEP8(Ks[buf], Js[buf], 8);
        if (hn) {
            *(float4*)&Js[nx][ln    ][lc] = tf32r4(nj0);
            *(float4*)&Js[nx][ln + 8][lc] = tf32r4(nj1);
        }
        __syncthreads();
        buf = nx;
    }
    float* Mp = g_Mp + ((size_t)(b * NSLICE + s) * DK) * DM;
#pragma unroll
    for (int im = 0; im < 4; im++)
#pragma unroll
    for (int jn = 0; jn < 4; jn++) {
        const int k = wm * 64 + im * 16 + g;
        const int c = d0 + wn * 32 + jn * 8 + 2 * tg;
        *(float2*)(Mp + (size_t)k * DM + c)       = make_float2(acc[im][jn][0], acc[im][jn][1]);
        *(float2*)(Mp + (size_t)(k + 8) * DM + c) = make_float2(acc[im][jn][2], acc[im][jn][3]);
    }
}

// ---------------------------------------------------------------------------
// Kernel 2b: reduce slices.  M[b][k][d] = sum_s Mp[b][s][k][d]
// ---------------------------------------------------------------------------
__global__ void __launch_bounds__(256) k_mred() {
    const size_t f = (size_t)blockIdx.x * 256 + threadIdx.x;  // float4 index
    const size_t base = f * 4;
    const size_t per_b = (size_t)DK * DM;
    const size_t b = base / per_b;
    const size_t rem = base % per_b;
    float4 acc = make_float4(0.f, 0.f, 0.f, 0.f);
#pragma unroll
    for (int s = 0; s < NSLICE; s++) {
        float4 v = *(const float4*)(g_Mp + (b * NSLICE + s) * per_b + rem);
        acc.x += v.x; acc.y += v.y; acc.z += v.z; acc.w += v.w;
    }
    *(float4*)(g_M + b * per_b + rem) = acc;
}

// ---------------------------------------------------------------------------
// Kernel 3: J_new[m][d] = (1/sqrt(128)) * sum_k Q[m][k]*M[b][k][d] + J[m][d]
// Tile 128x128, BK=16 -> 8 iters.
// ---------------------------------------------------------------------------
__global__ void __launch_bounds__(256, 2) k_out(const float* __restrict__ J) {
    __shared__ float As[2][16][PADW];   // [buf][k][m] (transposed Q tile)
    __shared__ float Bs[2][16][PADW];   // [buf][k][d]
    const int t  = threadIdx.x;
    const int m0 = blockIdx.x * 128;
    const int d0 = blockIdx.y * 128;
    const int b  = m0 / SEQ;

    const int lrA = t >> 1;            // 0..127 (m)
    const int lkA = (t & 1) << 2;      // 0 or 4 (k; +8 for 2nd half)
    const int lkB = t >> 4;            // 0..15  (k)
    const int lcB = (t & 15) << 3;     // 0..120 (d; two float4s)
    WARP_IDX();

    const float* Mb = g_M + (size_t)b * DK * DM + d0 + lcB;
    const float* qbase = g_Q + (size_t)(m0 + lrA) * DK + lkA;

    {   // prologue
        float4 a0 = tf32r4(*(const float4*)(qbase));
        float4 a1 = tf32r4(*(const float4*)(qbase + 8));
        STS_T4(As[0], lkA,     lrA, a0); STS_T4(As[0], lkA + 8, lrA, a1);
        *(float4*)&Bs[0][lkB][lcB    ] = tf32r4(*(const float4*)(Mb + (size_t)lkB * DM));
        *(float4*)&Bs[0][lkB][lcB + 4] = tf32r4(*(const float4*)(Mb + (size_t)lkB * DM + 4));
    }
    __syncthreads();

    float acc[4][4][4] = {};
    int buf = 0;
    for (int k0 = 0; k0 < DK; k0 += 16) {
        const bool hn = (k0 + 16) < DK;
        const int nx = buf ^ 1;
        float4 na0, na1;
        if (hn) {
            na0 = *(const float4*)(qbase + k0 + 16);
            na1 = *(const float4*)(qbase + k0 + 24);
        }
        MMA_STEP8(As[buf], Bs[buf], 0);
        float4 nb0, nb1;
        if (hn) {
            STS_T4(As[nx], lkA,     lrA, tf32r4(na0));
            STS_T4(As[nx], lkA + 8, lrA, tf32r4(na1));
            nb0 = *(const float4*)(Mb + (size_t)(k0 + 16 + lkB) * DM);
            nb1 = *(const float4*)(Mb + (size_t)(k0 + 16 + lkB) * DM + 4);
        }
        MMA_STEP8(As[buf], Bs[buf], 8);
        if (hn) {
            *(float4*)&Bs[nx][lkB][lcB    ] = tf32r4(nb0);
            *(float4*)&Bs[nx][lkB][lcB + 4] = tf32r4(nb1);
        }
        __syncthreads();
        buf = nx;
    }
    const float sc = 0.088388347648318447f;  // 1/sqrt(128)
#pragma unroll
    for (int im = 0; im < 4; im++)
#pragma unroll
    for (int jn = 0; jn < 4; jn++) {
        const size_t m  = (size_t)(m0 + wm * 64 + im * 16 + g);
        const int    dd = d0 + wn * 32 + jn * 8 + 2 * tg;
        float2 j0 = *(const float2*)(J + m * DM + dd);
        float2 j1 = *(const float2*)(J + (m + 8) * DM + dd);
        *(float2*)(g_Jn + m * DM + dd) =
            make_float2(acc[im][jn][0] * sc + j0.x, acc[im][jn][1] * sc + j0.y);
        *(float2*)(g_Jn + (m + 8) * DM + dd) =
            make_float2(acc[im][jn][2] * sc + j1.x, acc[im][jn][3] * sc + j1.y);
    }
}

// ---------------------------------------------------------------------------
// Kernel 4: LayerNorm over last dim (1024). One block (256 thr) per row.
// ---------------------------------------------------------------------------
__global__ void __launch_bounds__(256) k_ln(const float* __restrict__ gamma,
                                            const float* __restrict__ beta,
                                            float* __restrict__ out) {
    __shared__ float sred[8], ssred[8];
    const int t = threadIdx.x;
    const size_t row = blockIdx.x;
    const int dd = t << 2;

    float4 v = *(const float4*)(g_Jn + row * DM + dd);
    float s  = v.x + v.y + v.z + v.w;
    float ss = v.x * v.x + v.y * v.y + v.z * v.z + v.w * v.w;
#pragma unroll
    for (int o = 16; o > 0; o >>= 1) {
        s  += __shfl_xor_sync(0xffffffffu, s,  o);
        ss += __shfl_xor_sync(0xffffffffu, ss, o);
    }
    const int w = t >> 5;
    if ((t & 31) == 0) { sred[w] = s; ssred[w] = ss; }
    __syncthreads();
    s = 0.f; ss = 0.f;
#pragma unroll
    for (int i = 0; i < 8; i++) { s += sred[i]; ss += ssred[i]; }

    const float mean = s * (1.0f / DM);
    const float var  = ss * (1.0f / DM) - mean * mean;
    const float rstd = rsqrtf(var + 1e-5f);

    float4 g = *(const float4*)(gamma + dd);
    float4 b = *(const float4*)(beta + dd);
    float4 o;
    o.x = (v.x - mean) * rstd * g.x + b.x;
    o.y = (v.y - mean) * rstd * g.y + b.y;
    o.z = (v.z - mean) * rstd * g.z + b.z;
    o.w = (v.w - mean) * rstd * g.w + b.w;
    *(float4*)(out + row * DM + dd) = o;
}

// ---------------------------------------------------------------------------
extern "C" void kernel_launch(void* const* d_in, const int* in_sizes, int n_in,
                              void* d_out, int out_size) {
    (void)in_sizes; (void)n_in; (void)out_size;
    const float* J     = (const float*)d_in[0];
    const float* WQ    = (const float*)d_in[1];
    const float* WK    = (const float*)d_in[2];
    const float* gamma = (const float*)d_in[3];
    const float* beta  = (const float*)d_in[4];
    float* out = (float*)d_out;

    k_qk  <<<dim3(NB / 128, 2), 256>>>(J, WQ, WK);
    k_m   <<<dim3(DM / 128, NSLICE, BATCH), 256>>>(J);
    k_mred<<<(BATCH * DK * DM / 4) / 256, 256>>>();
    k_out <<<dim3(NB / 128, DM / 128), 256>>>(J);
    k_ln  <<<NB, 256>>>(gamma, beta, out);
}